// round 1
// baseline (speedup 1.0000x reference)
#include <cuda_runtime.h>
#include <math.h>

#define NN 50000
#define EE 600000
#define DD 128
#define GG 128

// ---------------- device scratch (no allocations allowed) ----------------
__device__ float g_h[NN * DD];        // h = x @ W
__device__ float g_xa[NN * DD];       // ping
__device__ float g_xb[NN * DD];       // pong
__device__ int   g_deg[NN];           // in-degree (real edges only)
__device__ int   g_fill[NN];          // CSR fill cursors
__device__ float g_dinv[NN];          // deg^-1/2 (incl. self loop)
__device__ int   g_rowptr[NN + 1];
__device__ int   g_csrc[EE];          // src node per CSR slot
__device__ float g_cw[EE];            // edge norm per CSR slot

// ---------------- CSR build ----------------
__global__ void k_init() {
    int i = blockIdx.x * blockDim.x + threadIdx.x;
    if (i < NN) { g_deg[i] = 0; g_fill[i] = 0; }
}

__global__ void k_deg(const int* __restrict__ ei) {
    int e = blockIdx.x * blockDim.x + threadIdx.x;
    if (e < EE) atomicAdd(&g_deg[ei[EE + e]], 1);
}

// single-block exclusive scan of g_deg -> g_rowptr
__global__ void k_scan() {
    const int CH = (NN + 1023) / 1024;  // 49
    __shared__ int ss[1024];
    int t = threadIdx.x;
    int vals[CH];
    int base = t * CH;
    int loc = 0;
#pragma unroll
    for (int i = 0; i < CH; ++i) {
        int idx = base + i;
        int v = (idx < NN) ? g_deg[idx] : 0;
        vals[i] = loc;
        loc += v;
    }
    ss[t] = loc;
    __syncthreads();
    for (int off = 1; off < 1024; off <<= 1) {
        int v = (t >= off) ? ss[t - off] : 0;
        __syncthreads();
        ss[t] += v;
        __syncthreads();
    }
    int pre = (t > 0) ? ss[t - 1] : 0;
#pragma unroll
    for (int i = 0; i < CH; ++i) {
        int idx = base + i;
        if (idx < NN) g_rowptr[idx] = pre + vals[i];
    }
    if (t == 1023) g_rowptr[NN] = ss[1023];
}

__global__ void k_dinv() {
    int i = blockIdx.x * blockDim.x + threadIdx.x;
    if (i < NN) g_dinv[i] = rsqrtf((float)(g_deg[i] + 1));  // +1 self loop
}

__global__ void k_fill(const int* __restrict__ ei) {
    int e = blockIdx.x * blockDim.x + threadIdx.x;
    if (e < EE) {
        int s = ei[e];
        int d = ei[EE + e];
        int pos = g_rowptr[d] + atomicAdd(&g_fill[d], 1);
        g_csrc[pos] = s;
        g_cw[pos] = g_dinv[s] * g_dinv[d];
    }
}

// ---------------- GEMM: H[N,128] = X[N,128] @ W[128,128] ----------------
// BM=64, BN=128, BK=32, 256 threads, each thread 4x8 micro-tile.
__global__ void __launch_bounds__(256) k_gemm(const float* __restrict__ X,
                                              const float* __restrict__ Wm) {
    __shared__ float xs[32][65];    // [k][m], pad 65 -> conflict-free transpose store
    __shared__ float ws[32][128];   // [k][n]
    int m0 = blockIdx.x * 64;
    int tid = threadIdx.x;
    int tx = tid & 15;     // col group
    int ty = tid >> 4;     // row group
    float acc[4][8];
#pragma unroll
    for (int r = 0; r < 4; ++r)
#pragma unroll
        for (int c = 0; c < 8; ++c) acc[r][c] = 0.f;

    for (int k0 = 0; k0 < 128; k0 += 32) {
        // load X chunk (64x32) transposed into xs
#pragma unroll
        for (int i = 0; i < 8; ++i) {
            int e = tid + i * 256;         // 0..2047
            int m = e >> 5, kk = e & 31;
            int gm = m0 + m;
            xs[kk][m] = (gm < NN) ? X[(size_t)gm * 128 + k0 + kk] : 0.f;
        }
        // load W chunk (32x128) as float4
#pragma unroll
        for (int i = 0; i < 4; ++i) {
            int e = tid + i * 256;         // 0..1023 float4 units
            int kk = e >> 5, nn = (e & 31) << 2;
            *(float4*)&ws[kk][nn] = *(const float4*)&Wm[(size_t)(k0 + kk) * 128 + nn];
        }
        __syncthreads();
#pragma unroll
        for (int kk = 0; kk < 32; ++kk) {
            float a[4];
#pragma unroll
            for (int r = 0; r < 4; ++r) a[r] = xs[kk][ty * 4 + r];
            float4 w0 = *(const float4*)&ws[kk][tx * 4];
            float4 w1 = *(const float4*)&ws[kk][64 + tx * 4];
#pragma unroll
            for (int r = 0; r < 4; ++r) {
                acc[r][0] += a[r] * w0.x; acc[r][1] += a[r] * w0.y;
                acc[r][2] += a[r] * w0.z; acc[r][3] += a[r] * w0.w;
                acc[r][4] += a[r] * w1.x; acc[r][5] += a[r] * w1.y;
                acc[r][6] += a[r] * w1.z; acc[r][7] += a[r] * w1.w;
            }
        }
        __syncthreads();
    }
#pragma unroll
    for (int r = 0; r < 4; ++r) {
        int gm = m0 + ty * 4 + r;
        if (gm < NN) {
            float4 v0 = make_float4(acc[r][0], acc[r][1], acc[r][2], acc[r][3]);
            float4 v1 = make_float4(acc[r][4], acc[r][5], acc[r][6], acc[r][7]);
            *(float4*)&g_h[(size_t)gm * 128 + tx * 4] = v0;
            *(float4*)&g_h[(size_t)gm * 128 + 64 + tx * 4] = v1;
        }
    }
}

// ---------------- fused aggregate + bias + LayerNorm + residual + SiLU ----------------
// one warp per node; lane holds 4 consecutive features (float4)
__global__ void __launch_bounds__(256) k_agg(const float* __restrict__ xin,
                                             const float* __restrict__ b,
                                             const float* __restrict__ gw,
                                             const float* __restrict__ be,
                                             float* __restrict__ y) {
    int w = (blockIdx.x * blockDim.x + threadIdx.x) >> 5;
    int lane = threadIdx.x & 31;
    if (w >= NN) return;
    int col = lane * 4;

    const float* h = g_h;
    float di = g_dinv[w];
    float sw = di * di;  // self-loop norm
    float4 acc = *(const float4*)(h + (size_t)w * DD + col);
    acc.x *= sw; acc.y *= sw; acc.z *= sw; acc.w *= sw;

    int e0 = g_rowptr[w], e1 = g_rowptr[w + 1];
    for (int e = e0; e < e1; ++e) {
        int s = __ldg(&g_csrc[e]);
        float wt = __ldg(&g_cw[e]);
        float4 hs = *(const float4*)(h + (size_t)s * DD + col);
        acc.x += wt * hs.x; acc.y += wt * hs.y;
        acc.z += wt * hs.z; acc.w += wt * hs.w;
    }
    float4 bv = *(const float4*)(b + col);
    acc.x += bv.x; acc.y += bv.y; acc.z += bv.z; acc.w += bv.w;

    // mean over 128
    float s1 = acc.x + acc.y + acc.z + acc.w;
#pragma unroll
    for (int o = 16; o; o >>= 1) s1 += __shfl_xor_sync(0xffffffffu, s1, o);
    float mu = s1 * (1.f / 128.f);

    float d0 = acc.x - mu, d1 = acc.y - mu, d2 = acc.z - mu, d3 = acc.w - mu;
    float s2 = d0 * d0 + d1 * d1 + d2 * d2 + d3 * d3;
#pragma unroll
    for (int o = 16; o; o >>= 1) s2 += __shfl_xor_sync(0xffffffffu, s2, o);
    float rs = rsqrtf(s2 * (1.f / 128.f) + 1e-5f);

    float4 gv = *(const float4*)(gw + col);
    float4 bev = *(const float4*)(be + col);
    float4 xv = *(const float4*)(xin + (size_t)w * DD + col);

    float v0 = d0 * rs * gv.x + bev.x + xv.x;
    float v1 = d1 * rs * gv.y + bev.y + xv.y;
    float v2 = d2 * rs * gv.z + bev.z + xv.z;
    float v3 = d3 * rs * gv.w + bev.w + xv.w;

    v0 = v0 / (1.f + expf(-v0));
    v1 = v1 / (1.f + expf(-v1));
    v2 = v2 / (1.f + expf(-v2));
    v3 = v3 / (1.f + expf(-v3));

    *(float4*)(y + (size_t)w * DD + col) = make_float4(v0, v1, v2, v3);
}

// ---------------- global mean pool ----------------
__device__ __forceinline__ int lowerb(const int* __restrict__ a, int n, int key) {
    int lo = 0, hi = n;
    while (lo < hi) {
        int mid = (lo + hi) >> 1;
        if (a[mid] < key) lo = mid + 1; else hi = mid;
    }
    return lo;
}

__global__ void __launch_bounds__(128) k_pool(const float* __restrict__ x,
                                              const int* __restrict__ batch,
                                              float* __restrict__ out) {
    __shared__ int sl, sh;
    int g = blockIdx.x;
    if (threadIdx.x == 0) {
        sl = lowerb(batch, NN, g);
        sh = lowerb(batch, NN, g + 1);
    }
    __syncthreads();
    int lo = sl, hi = sh;
    int c = threadIdx.x;
    float sum = 0.f;
    for (int n = lo; n < hi; ++n) sum += x[(size_t)n * DD + c];
    out[g * DD + c] = sum / fmaxf((float)(hi - lo), 1.f);
}

// ---------------- launch ----------------
extern "C" void kernel_launch(void* const* d_in, const int* in_sizes, int n_in,
                              void* d_out, int out_size) {
    const float* x     = (const float*)d_in[0];
    const int*   ei    = (const int*)d_in[1];
    const int*   batch = (const int*)d_in[2];
    const float* W[3]  = {(const float*)d_in[3],  (const float*)d_in[7],  (const float*)d_in[11]};
    const float* b[3]  = {(const float*)d_in[4],  (const float*)d_in[8],  (const float*)d_in[12]};
    const float* g[3]  = {(const float*)d_in[5],  (const float*)d_in[9],  (const float*)d_in[13]};
    const float* be[3] = {(const float*)d_in[6],  (const float*)d_in[10], (const float*)d_in[14]};
    float* out = (float*)d_out;

    float *pa = nullptr, *pb = nullptr;
    cudaGetSymbolAddress((void**)&pa, g_xa);
    cudaGetSymbolAddress((void**)&pb, g_xb);

    // CSR build (per call: deterministic work)
    k_init<<<(NN + 255) / 256, 256>>>();
    k_deg<<<(EE + 255) / 256, 256>>>(ei);
    k_scan<<<1, 1024>>>();
    k_dinv<<<(NN + 255) / 256, 256>>>();
    k_fill<<<(EE + 255) / 256, 256>>>(ei);

    const int gemm_blocks = (NN + 63) / 64;
    const int agg_blocks = (NN * 32 + 255) / 256;

    // layer 0: x -> pa
    k_gemm<<<gemm_blocks, 256>>>(x, W[0]);
    k_agg<<<agg_blocks, 256>>>(x, b[0], g[0], be[0], pa);
    // layer 1: pa -> pb
    k_gemm<<<gemm_blocks, 256>>>(pa, W[1]);
    k_agg<<<agg_blocks, 256>>>(pa, b[1], g[1], be[1], pb);
    // layer 2: pb -> pa
    k_gemm<<<gemm_blocks, 256>>>(pb, W[2]);
    k_agg<<<agg_blocks, 256>>>(pb, b[2], g[2], be[2], pa);

    k_pool<<<GG, 128>>>(pa, batch, out);
}